// round 5
// baseline (speedup 1.0000x reference)
#include <cuda_runtime.h>
#include <math.h>

#define BB    64
#define TC    288
#define TF    12
#define DD    16
#define NLAY  4
#define LMAX  300
#define NTHR  384   /* 12 warps: 3 per SMSP, even FMA-pipe load in attention */

// KV cache for decode, head-major planes: [b][l][h][pos] as float4. Static: no allocation.
__device__ float g_kc[(size_t)BB * NLAY * 4 * LMAX * 4];
__device__ float g_vc[(size_t)BB * NLAY * 4 * LMAX * 4];

// ---- shared memory layout (float offsets) ----
#define OFF_WQKV 0        /* [4][48][16] */
#define OFF_BQKV 3072
#define OFF_WO   3264     /* [4][16][16] */
#define OFF_BO   4288
#define OFF_CBO  4352
#define OFF_LN1G 4416
#define OFF_LN1B 4480
#define OFF_LN2G 4544
#define OFF_LN2B 4608
#define OFF_LN3G 4672
#define OFF_LN3B 4736
#define OFF_FW1  4800     /* [4][64][16] */
#define OFF_FB1  8896
#define OFF_FW2  9152     /* TRANSPOSED: [4][64][16], W2T[j][d] = fW2[d][j] */
#define OFF_FB2  13248
#define OFF_FUSW 13312    /* [16][48] */
#define OFF_FUSB 14080
#define OFF_OUTW 14096
#define OFF_MISC 14112
#define OFF_X    14368    /* 288 rows, stride 20 floats (80B, conflict-free) */
#define OFF_Q    20128
#define OFF_K    25888
#define OFF_V    31648
#define SMEM_FLOATS 37408
#define SMEM_BYTES  (SMEM_FLOATS * 4)

#define M_NT   (OFF_MISC + 0)
#define M_S    (OFF_MISC + 1)
#define M_OUTB (OFF_MISC + 2)
#define M_XC   (OFF_MISC + 16)
#define M_QS   (OFF_MISC + 32)
#define M_ATT  (OFF_MISC + 48)
#define M_WC   (OFF_MISC + 64)
#define M_H1   (OFF_MISC + 80)
#define M_RED  (OFF_MISC + 144)

// exp(x) with the 1/ln2 factor pre-folded into q: e = 2^sc, one MUFU.EX2.
__device__ __forceinline__ float ex2(float x) {
    float r;
    asm("ex2.approx.f32 %0, %1;" : "=f"(r) : "f"(x));
    return r;
}

__device__ __forceinline__ void ld4(float* d, const float* s) {
    float4 u = *(const float4*)s; d[0]=u.x; d[1]=u.y; d[2]=u.z; d[3]=u.w;
}
__device__ __forceinline__ void st4(float* d, const float* s) {
    *(float4*)d = make_float4(s[0], s[1], s[2], s[3]);
}
__device__ __forceinline__ float dot16(const float* x, const float* w) {
    float acc = 0.f;
#pragma unroll
    for (int c = 0; c < 4; ++c) {
        float4 u = *(const float4*)(w + 4 * c);
        acc += x[4*c]*u.x + x[4*c+1]*u.y + x[4*c+2]*u.z + x[4*c+3]*u.w;
    }
    return acc;
}
// LayerNorm over a 16-element register vector (per-thread serial)
__device__ __forceinline__ void lnvec(float* v, const float* g, const float* bta) {
    float m = 0.f;
#pragma unroll
    for (int d = 0; d < 16; ++d) m += v[d];
    m *= (1.f/16.f);
    float var = 0.f;
#pragma unroll
    for (int d = 0; d < 16; ++d) { float t = v[d]-m; var += t*t; }
    var *= (1.f/16.f);
    float inv = rsqrtf(var + 1e-5f);
#pragma unroll
    for (int d = 0; d < 16; ++d) v[d] = (v[d]-m)*inv*g[d] + bta[d];
}
// LayerNorm over 16 values spread across lanes 0..15 (lanes 16..31 duplicate)
__device__ __forceinline__ float ln16_shfl(float v, int d, const float* g, const float* bta) {
    float s = v;
    s += __shfl_xor_sync(0xffffffffu, s, 8);
    s += __shfl_xor_sync(0xffffffffu, s, 4);
    s += __shfl_xor_sync(0xffffffffu, s, 2);
    s += __shfl_xor_sync(0xffffffffu, s, 1);
    float m = s * (1.f/16.f);
    float dd = v - m;
    float q = dd * dd;
    q += __shfl_xor_sync(0xffffffffu, q, 8);
    q += __shfl_xor_sync(0xffffffffu, q, 4);
    q += __shfl_xor_sync(0xffffffffu, q, 2);
    q += __shfl_xor_sync(0xffffffffu, q, 1);
    return dd * rsqrtf(q * (1.f/16.f) + 1e-5f) * g[d] + bta[d];
}

extern __shared__ float sm[];

__global__ __launch_bounds__(NTHR, 1)
void mbar_decoder_kernel(
    const float* __restrict__ b1, const float* __restrict__ b2, const float* __restrict__ b3,
    const float* __restrict__ fusW, const float* __restrict__ fusB,
    const float* __restrict__ posE,
    const float* __restrict__ Wqkv, const float* __restrict__ bqkv,
    const float* __restrict__ Wo,   const float* __restrict__ bo,
    const float* __restrict__ cbo,
    const float* __restrict__ ln1g, const float* __restrict__ ln1b,
    const float* __restrict__ ln2g, const float* __restrict__ ln2b,
    const float* __restrict__ ln3g, const float* __restrict__ ln3b,
    const float* __restrict__ fW1,  const float* __restrict__ fb1,
    const float* __restrict__ fW2,  const float* __restrict__ fb2,
    const float* __restrict__ outW, const float* __restrict__ outB,
    float* __restrict__ out)
{
    const int b   = blockIdx.x;
    const int tid = threadIdx.x;

    // Fold softmax scale (1/sqrt(4)=0.5) and 1/ln(2) into q: e^(0.5*qk) = 2^(QSC*q · k)
    const float QSC = 0.72134752044f;   // 0.5 * log2(e)

    // ---- stage all weights into smem (fW2 transposed to [j][d]) ----
    for (int i = tid; i < 3072; i += NTHR) sm[OFF_WQKV + i] = Wqkv[i];
    for (int i = tid; i < 192;  i += NTHR) sm[OFF_BQKV + i] = bqkv[i];
    for (int i = tid; i < 1024; i += NTHR) sm[OFF_WO   + i] = Wo[i];
    for (int i = tid; i < 4096; i += NTHR) sm[OFF_FW1  + i] = fW1[i];
    for (int i = tid; i < 256;  i += NTHR) sm[OFF_FB1  + i] = fb1[i];
    for (int i = tid; i < 4096; i += NTHR) {
        const int l = i >> 10, r = i & 1023;   // r = d*64 + j in source
        const int d = r >> 6,  j = r & 63;
        sm[OFF_FW2 + l*1024 + j*16 + d] = fW2[i];
    }
    for (int i = tid; i < 768;  i += NTHR) sm[OFF_FUSW + i] = fusW[i];
    if (tid < 64) {
        sm[OFF_BO  +tid]=bo[tid];   sm[OFF_CBO +tid]=cbo[tid];
        sm[OFF_LN1G+tid]=ln1g[tid]; sm[OFF_LN1B+tid]=ln1b[tid];
        sm[OFF_LN2G+tid]=ln2g[tid]; sm[OFF_LN2B+tid]=ln2b[tid];
        sm[OFF_LN3G+tid]=ln3g[tid]; sm[OFF_LN3B+tid]=ln3b[tid];
        sm[OFF_FB2 +tid]=fb2[tid];
    }
    if (tid < 16) { sm[OFF_FUSB+tid]=fusB[tid]; sm[OFF_OUTW+tid]=outW[tid]; }
    if (tid == 0) {
        float s = 0.f;
#pragma unroll
        for (int d = 0; d < 16; ++d) { float w = outW[d]; s += w*w; }
        sm[M_S] = s; sm[M_OUTB] = outB[0];
    }
    __syncthreads();

    // ---- branch fusion + positional embedding (one token per thread, 288 active) ----
    if (tid < TC) {
        const int t = tid;
        float cr[48];
        const float* p1 = b1 + ((size_t)b*TC + t)*DD;
        const float* p2 = b2 + ((size_t)b*TC + t)*DD;
        const float* p3 = b3 + ((size_t)b*TC + t)*DD;
#pragma unroll
        for (int c = 0; c < 4; ++c) { ld4(cr+4*c, p1+4*c); ld4(cr+16+4*c, p2+4*c); ld4(cr+32+4*c, p3+4*c); }
#pragma unroll
        for (int d = 0; d < 16; ++d) {
            float acc = sm[OFF_FUSB + d];
#pragma unroll
            for (int jc = 0; jc < 12; ++jc) {
                float4 w = *(const float4*)&sm[OFF_FUSW + d*48 + 4*jc];
                acc += cr[4*jc]*w.x + cr[4*jc+1]*w.y + cr[4*jc+2]*w.z + cr[4*jc+3]*w.w;
            }
            sm[OFF_X + t*20 + d] = acc + posE[t*DD + d];
        }
    }
    __syncthreads();

    const size_t plane = ((size_t)b*NLAY) * 4;  // +l*4+h per use

    // =============== PREFILL: 4 layers over 288 tokens ===============
#pragma unroll 1
    for (int l = 0; l < NLAY; ++l) {
        // QKV projection (one token per thread); K/V -> smem + global head planes
        if (tid < TC) {
            const int t = tid;
            float xr[16];
#pragma unroll
            for (int c = 0; c < 4; ++c) ld4(xr+4*c, &sm[OFF_X + t*20 + 4*c]);
            const float* W  = &sm[OFF_WQKV + l*768];
            const float* Bq = &sm[OFF_BQKV + l*48];
            float kv[32];
#pragma unroll
            for (int j = 0; j < 16; ++j) sm[OFF_Q + t*20 + j] = Bq[j] + dot16(xr, W + j*16);
#pragma unroll
            for (int j = 0; j < 16; ++j) kv[j]    = Bq[16+j] + dot16(xr, W + (16+j)*16);
#pragma unroll
            for (int j = 0; j < 16; ++j) kv[16+j] = Bq[32+j] + dot16(xr, W + (32+j)*16);
#pragma unroll
            for (int c = 0; c < 4; ++c) { st4(&sm[OFF_K + t*20 + 4*c], kv+4*c); st4(&sm[OFF_V + t*20 + 4*c], kv+16+4*c); }
            float4* gk = (float4*)g_kc;
            float4* gv = (float4*)g_vc;
#pragma unroll
            for (int h = 0; h < 4; ++h) {
                gk[(plane + l*4 + h)*LMAX + t] = make_float4(kv[4*h], kv[4*h+1], kv[4*h+2], kv[4*h+3]);
                gv[(plane + l*4 + h)*LMAX + t] = make_float4(kv[16+4*h], kv[16+4*h+1], kv[16+4*h+2], kv[16+4*h+3]);
            }
        }
        __syncthreads();

        // causal attention: 1152 (token,head) items, 3 per thread (384 threads).
        // {tid, 1151-tid} pair costs a constant 289 key-iters; middle band
        // 384+tid varies slowly and interleaves across SMSPs by warp%4.
        {
            const int items[3] = { tid, 1151 - tid, 384 + tid };
#pragma unroll 1
            for (int it = 0; it < 3; ++it) {
                const int item = items[it];
                const int t = item >> 2;
                const int h = item & 3;
                float4 q4 = *(const float4*)&sm[OFF_Q + t*20 + 4*h];
                q4.x *= QSC; q4.y *= QSC; q4.z *= QSC; q4.w *= QSC;
                float s = 0.f, a0 = 0.f, a1 = 0.f, a2 = 0.f, a3 = 0.f;
                const float* kb = &sm[OFF_K + 4*h];
                const float* vb = &sm[OFF_V + 4*h];
#pragma unroll 4
                for (int k = 0; k <= t; ++k) {
                    float4 k4 = *(const float4*)(kb + k*20);
                    float4 v4 = *(const float4*)(vb + k*20);
                    float e = ex2(q4.x*k4.x + q4.y*k4.y + q4.z*k4.z + q4.w*k4.w);
                    s += e; a0 += e*v4.x; a1 += e*v4.y; a2 += e*v4.z; a3 += e*v4.w;
                }
                float inv = 1.f / s;
                *(float4*)&sm[OFF_Q + t*20 + 4*h] = make_float4(a0*inv, a1*inv, a2*inv, a3*inv);
            }
        }
        __syncthreads();

        // out-proj + LN1 + cross-bias + LN2 + FFN + LN3 (one token per thread)
        if (tid < TC) {
            const int t = tid;
            float ar[16], xr[16], w[16];
#pragma unroll
            for (int c = 0; c < 4; ++c) { ld4(ar+4*c, &sm[OFF_Q + t*20 + 4*c]); ld4(xr+4*c, &sm[OFF_X + t*20 + 4*c]); }
            const float* WoL = &sm[OFF_WO + l*256];
#pragma unroll
            for (int d = 0; d < 16; ++d) w[d] = xr[d] + sm[OFF_BO + l*16 + d] + dot16(ar, WoL + d*16);
            lnvec(w, &sm[OFF_LN1G + l*16], &sm[OFF_LN1B + l*16]);
#pragma unroll
            for (int d = 0; d < 16; ++d) w[d] += sm[OFF_CBO + l*16 + d];
            lnvec(w, &sm[OFF_LN2G + l*16], &sm[OFF_LN2B + l*16]);
            // FFN: on-the-fly rank-1 accumulation (W2 transposed), no h1[] array
            const float* W1  = &sm[OFF_FW1 + l*1024];
            const float* W2T = &sm[OFF_FW2 + l*1024];
            float o[16];
#pragma unroll
            for (int d = 0; d < 16; ++d) o[d] = w[d] + sm[OFF_FB2 + l*16 + d];
#pragma unroll 4
            for (int j = 0; j < 64; ++j) {
                float h = fmaxf(sm[OFF_FB1 + l*64 + j] + dot16(w, W1 + j*16), 0.f);
                float4 u0 = *(const float4*)(W2T + j*16 + 0);
                float4 u1 = *(const float4*)(W2T + j*16 + 4);
                float4 u2 = *(const float4*)(W2T + j*16 + 8);
                float4 u3 = *(const float4*)(W2T + j*16 + 12);
                o[0]+=h*u0.x; o[1]+=h*u0.y; o[2]+=h*u0.z; o[3]+=h*u0.w;
                o[4]+=h*u1.x; o[5]+=h*u1.y; o[6]+=h*u1.z; o[7]+=h*u1.w;
                o[8]+=h*u2.x; o[9]+=h*u2.y; o[10]+=h*u2.z; o[11]+=h*u2.w;
                o[12]+=h*u3.x; o[13]+=h*u3.y; o[14]+=h*u3.z; o[15]+=h*u3.w;
            }
            lnvec(o, &sm[OFF_LN3G + l*16], &sm[OFF_LN3B + l*16]);
#pragma unroll
            for (int c = 0; c < 4; ++c) st4(&sm[OFF_X + t*20 + 4*c], o+4*c);
        }
        __syncthreads();
    }

    // first next-token (prefill last position) + output 0
    if (tid == 0) {
        float acc = sm[M_OUTB];
#pragma unroll
        for (int d = 0; d < 16; ++d) acc += sm[OFF_X + (TC-1)*20 + d] * sm[OFF_OUTW + d];
        sm[M_NT] = acc;
        out[b*TF + 0] = acc * sm[M_S] + sm[M_OUTB];
    }

    // =============== DECODE: 11 single-token KV-cache steps ===============
#pragma unroll 1
    for (int step = 1; step < TF; ++step) {
        const int p = TC - 1 + step;   // position of the new token
        __syncthreads();               // M_NT ready; prior M_XC consumers done
        if (tid < 16) sm[M_XC + tid] = sm[M_NT] * sm[OFF_OUTW + tid] + posE[p*DD + tid];
        __syncthreads();

#pragma unroll 1
        for (int l = 0; l < NLAY; ++l) {
            // QKV for the single token; K/V appended to global head planes
            if (tid < 48) {
                const int j = tid;
                const float* W = &sm[OFF_WQKV + l*768 + j*16];
                float acc = sm[OFF_BQKV + l*48 + j];
#pragma unroll
                for (int i = 0; i < 16; ++i) acc += sm[M_XC + i] * W[i];
                if (j < 16) {
                    sm[M_QS + j] = acc;
                } else if (j < 32) {
                    const int e = j - 16, h = e >> 2, c = e & 3;
                    g_kc[((plane + l*4 + h)*LMAX + p)*4 + c] = acc;
                } else {
                    const int e = j - 32, h = e >> 2, c = e & 3;
                    g_vc[((plane + l*4 + h)*LMAX + p)*4 + c] = acc;
                }
            }
            __syncthreads();

            // attention over cache: 64 threads per head, coalesced plane reads
            {
                float s = 0.f, a0 = 0.f, a1 = 0.f, a2 = 0.f, a3 = 0.f;
                if (tid < 256) {
                    const int h  = tid >> 6;
                    const int jj = tid & 63;
                    float4 q4 = *(const float4*)&sm[M_QS + 4*h];
                    q4.x *= QSC; q4.y *= QSC; q4.z *= QSC; q4.w *= QSC;
                    const float4* Kb = (const float4*)g_kc + (plane + l*4 + h)*LMAX;
                    const float4* Vb = (const float4*)g_vc + (plane + l*4 + h)*LMAX;
                    for (int k = jj; k <= p; k += 64) {
                        float4 k4 = Kb[k];
                        float4 v4 = Vb[k];
                        float e = ex2(q4.x*k4.x + q4.y*k4.y + q4.z*k4.z + q4.w*k4.w);
                        s += e; a0 += e*v4.x; a1 += e*v4.y; a2 += e*v4.z; a3 += e*v4.w;
                    }
                }
#pragma unroll
                for (int off = 16; off >= 1; off >>= 1) {
                    s  += __shfl_xor_sync(0xffffffffu, s,  off);
                    a0 += __shfl_xor_sync(0xffffffffu, a0, off);
                    a1 += __shfl_xor_sync(0xffffffffu, a1, off);
                    a2 += __shfl_xor_sync(0xffffffffu, a2, off);
                    a3 += __shfl_xor_sync(0xffffffffu, a3, off);
                }
                if (tid < 256 && (tid & 31) == 0) {
                    float* r = &sm[M_RED + (tid >> 5)*5];
                    r[0]=s; r[1]=a0; r[2]=a1; r[3]=a2; r[4]=a3;
                }
            }
            __syncthreads();

            // head combine + out-proj + LN1 + cbo + LN2 on warp 0
            if (tid < 32) {
                if (tid < 16) {
                    const int h = tid >> 2, c = tid & 3;
                    const float* r0 = &sm[M_RED + (2*h)*5];
                    const float* r1 = &sm[M_RED + (2*h+1)*5];
                    sm[M_ATT + tid] = (r0[1+c] + r1[1+c]) / (r0[0] + r1[0]);
                }
                __syncwarp(0xffffffffu);
                const int d = tid & 15;
                float w = sm[M_XC + d] + sm[OFF_BO + l*16 + d]
                        + dot16(&sm[M_ATT], &sm[OFF_WO + l*256 + d*16]);
                w = ln16_shfl(w, d, &sm[OFF_LN1G + l*16], &sm[OFF_LN1B + l*16]);
                w += sm[OFF_CBO + l*16 + d];
                w = ln16_shfl(w, d, &sm[OFF_LN2G + l*16], &sm[OFF_LN2B + l*16]);
                sm[M_WC + d] = w;
            }
            __syncthreads();
            if (tid < 64) {   // FFN hidden
                float h = sm[OFF_FB1 + l*64 + tid] + dot16(&sm[M_WC], &sm[OFF_FW1 + l*1024 + tid*16]);
                sm[M_H1 + tid] = fmaxf(h, 0.f);
            }
            __syncthreads();
            if (tid < 32) {   // FFN out (transposed W2) + LN3 -> next layer input
                const int d = tid & 15;
                float o = sm[M_WC + d] + sm[OFF_FB2 + l*16 + d];
                const float* W2T = &sm[OFF_FW2 + l*1024];
#pragma unroll 8
                for (int j = 0; j < 64; ++j) o += sm[M_H1 + j] * W2T[j*16 + d];
                o = ln16_shfl(o, d, &sm[OFF_LN3G + l*16], &sm[OFF_LN3B + l*16]);
                sm[M_XC + d] = o;
            }
            __syncthreads();
        }

        if (tid == 0) {
            float acc = sm[M_OUTB];
#pragma unroll
            for (int d = 0; d < 16; ++d) acc += sm[M_XC + d] * sm[OFF_OUTW + d];
            sm[M_NT] = acc;
            out[b*TF + step] = acc * sm[M_S] + sm[M_OUTB];
        }
    }
}

extern "C" void kernel_launch(void* const* d_in, const int* in_sizes, int n_in,
                              void* d_out, int out_size) {
    (void)in_sizes; (void)n_in; (void)out_size;
    cudaFuncSetAttribute(mbar_decoder_kernel,
                         cudaFuncAttributeMaxDynamicSharedMemorySize, SMEM_BYTES);
    mbar_decoder_kernel<<<BB, NTHR, SMEM_BYTES>>>(
        (const float*)d_in[0],  (const float*)d_in[1],  (const float*)d_in[2],
        (const float*)d_in[3],  (const float*)d_in[4],  (const float*)d_in[5],
        (const float*)d_in[6],  (const float*)d_in[7],  (const float*)d_in[8],
        (const float*)d_in[9],  (const float*)d_in[10],
        (const float*)d_in[11], (const float*)d_in[12],
        (const float*)d_in[13], (const float*)d_in[14],
        (const float*)d_in[15], (const float*)d_in[16],
        (const float*)d_in[17], (const float*)d_in[18],
        (const float*)d_in[19], (const float*)d_in[20],
        (const float*)d_in[21], (const float*)d_in[22],
        (float*)d_out);
}

// round 13
// speedup vs baseline: 1.5607x; 1.5607x over previous
#include <cuda_runtime.h>
#include <math.h>

#define BB    64
#define TC    288
#define TF    12
#define DD    16
#define NLAY  4
#define LMAX  300
#define NTHR  576   /* 18 warps; attention: 2 items/thread, exactly 289 key-iters each */

// KV cache for decode, head-major planes: [b][l][h][pos] as float4. Static: no allocation.
__device__ float g_kc[(size_t)BB * NLAY * 4 * LMAX * 4];
__device__ float g_vc[(size_t)BB * NLAY * 4 * LMAX * 4];

// ---- shared memory layout (float offsets) ----
#define OFF_WQKV 0        /* [4][48][16] */
#define OFF_BQKV 3072
#define OFF_WO   3264     /* [4][16][16] */
#define OFF_BO   4288
#define OFF_CBO  4352
#define OFF_LN1G 4416
#define OFF_LN1B 4480
#define OFF_LN2G 4544
#define OFF_LN2B 4608
#define OFF_LN3G 4672
#define OFF_LN3B 4736
#define OFF_FW1  4800     /* [4][64][16] */
#define OFF_FB1  8896
#define OFF_FW2  9152     /* TRANSPOSED: [4][64][16], W2T[j][d] = fW2[d][j] */
#define OFF_FB2  13248
#define OFF_FUSW 13312    /* [16][48] */
#define OFF_FUSB 14080
#define OFF_OUTW 14096
#define OFF_MISC 14112
#define OFF_X    14368    /* 288 rows, stride 20 floats (80B, conflict-free) */
#define OFF_Q    20128
#define OFF_K    25888
#define OFF_V    31648
#define SMEM_FLOATS 37408
#define SMEM_BYTES  (SMEM_FLOATS * 4)

#define M_NT   (OFF_MISC + 0)
#define M_S    (OFF_MISC + 1)
#define M_OUTB (OFF_MISC + 2)
#define M_XC   (OFF_MISC + 16)
#define M_QS   (OFF_MISC + 32)
#define M_ATT  (OFF_MISC + 48)
#define M_WC   (OFF_MISC + 64)
#define M_H1   (OFF_MISC + 80)
#define M_RED  (OFF_MISC + 144)

// exp(x) with scale and 1/ln2 pre-folded into q: e = 2^sc, one MUFU.EX2.
__device__ __forceinline__ float ex2(float x) {
    float r;
    asm("ex2.approx.f32 %0, %1;" : "=f"(r) : "f"(x));
    return r;
}
// Named barrier among the first 256 threads (warps 8..17 have exited).
__device__ __forceinline__ void bar256() {
    asm volatile("bar.sync 1, 256;" ::: "memory");
}

__device__ __forceinline__ void ld4(float* d, const float* s) {
    float4 u = *(const float4*)s; d[0]=u.x; d[1]=u.y; d[2]=u.z; d[3]=u.w;
}
__device__ __forceinline__ void st4(float* d, const float* s) {
    *(float4*)d = make_float4(s[0], s[1], s[2], s[3]);
}
__device__ __forceinline__ float dot16(const float* x, const float* w) {
    float acc = 0.f;
#pragma unroll
    for (int c = 0; c < 4; ++c) {
        float4 u = *(const float4*)(w + 4 * c);
        acc += x[4*c]*u.x + x[4*c+1]*u.y + x[4*c+2]*u.z + x[4*c+3]*u.w;
    }
    return acc;
}
// LayerNorm over a 16-element register vector (per-thread serial)
__device__ __forceinline__ void lnvec(float* v, const float* g, const float* bta) {
    float m = 0.f;
#pragma unroll
    for (int d = 0; d < 16; ++d) m += v[d];
    m *= (1.f/16.f);
    float var = 0.f;
#pragma unroll
    for (int d = 0; d < 16; ++d) { float t = v[d]-m; var += t*t; }
    var *= (1.f/16.f);
    float inv = rsqrtf(var + 1e-5f);
#pragma unroll
    for (int d = 0; d < 16; ++d) v[d] = (v[d]-m)*inv*g[d] + bta[d];
}
// LayerNorm over 16 values spread across lanes 0..15 (lanes 16..31 duplicate)
__device__ __forceinline__ float ln16_shfl(float v, int d, const float* g, const float* bta) {
    float s = v;
    s += __shfl_xor_sync(0xffffffffu, s, 8);
    s += __shfl_xor_sync(0xffffffffu, s, 4);
    s += __shfl_xor_sync(0xffffffffu, s, 2);
    s += __shfl_xor_sync(0xffffffffu, s, 1);
    float m = s * (1.f/16.f);
    float dd = v - m;
    float q = dd * dd;
    q += __shfl_xor_sync(0xffffffffu, q, 8);
    q += __shfl_xor_sync(0xffffffffu, q, 4);
    q += __shfl_xor_sync(0xffffffffu, q, 2);
    q += __shfl_xor_sync(0xffffffffu, q, 1);
    return dd * rsqrtf(q * (1.f/16.f) + 1e-5f) * g[d] + bta[d];
}

extern __shared__ float sm[];

__global__ __launch_bounds__(NTHR, 1)
void mbar_decoder_kernel(
    const float* __restrict__ b1, const float* __restrict__ b2, const float* __restrict__ b3,
    const float* __restrict__ fusW, const float* __restrict__ fusB,
    const float* __restrict__ posE,
    const float* __restrict__ Wqkv, const float* __restrict__ bqkv,
    const float* __restrict__ Wo,   const float* __restrict__ bo,
    const float* __restrict__ cbo,
    const float* __restrict__ ln1g, const float* __restrict__ ln1b,
    const float* __restrict__ ln2g, const float* __restrict__ ln2b,
    const float* __restrict__ ln3g, const float* __restrict__ ln3b,
    const float* __restrict__ fW1,  const float* __restrict__ fb1,
    const float* __restrict__ fW2,  const float* __restrict__ fb2,
    const float* __restrict__ outW, const float* __restrict__ outB,
    float* __restrict__ out)
{
    const int b   = blockIdx.x;
    const int tid = threadIdx.x;

    const float QSC = 0.72134752044f;   // 0.5 * log2(e): softmax scale folded into exp2 base

    // ---- stage all weights into smem (fW2 transposed to [j][d]) ----
    for (int i = tid; i < 3072; i += NTHR) sm[OFF_WQKV + i] = Wqkv[i];
    for (int i = tid; i < 192;  i += NTHR) sm[OFF_BQKV + i] = bqkv[i];
    for (int i = tid; i < 1024; i += NTHR) sm[OFF_WO   + i] = Wo[i];
    for (int i = tid; i < 4096; i += NTHR) sm[OFF_FW1  + i] = fW1[i];
    for (int i = tid; i < 256;  i += NTHR) sm[OFF_FB1  + i] = fb1[i];
    for (int i = tid; i < 4096; i += NTHR) {
        const int l = i >> 10, r = i & 1023;   // r = d*64 + j in source
        const int d = r >> 6,  j = r & 63;
        sm[OFF_FW2 + l*1024 + j*16 + d] = fW2[i];
    }
    for (int i = tid; i < 768;  i += NTHR) sm[OFF_FUSW + i] = fusW[i];
    if (tid < 64) {
        sm[OFF_BO  +tid]=bo[tid];   sm[OFF_CBO +tid]=cbo[tid];
        sm[OFF_LN1G+tid]=ln1g[tid]; sm[OFF_LN1B+tid]=ln1b[tid];
        sm[OFF_LN2G+tid]=ln2g[tid]; sm[OFF_LN2B+tid]=ln2b[tid];
        sm[OFF_LN3G+tid]=ln3g[tid]; sm[OFF_LN3B+tid]=ln3b[tid];
        sm[OFF_FB2 +tid]=fb2[tid];
    }
    if (tid < 16) { sm[OFF_FUSB+tid]=fusB[tid]; sm[OFF_OUTW+tid]=outW[tid]; }
    if (tid == 0) {
        float s = 0.f;
#pragma unroll
        for (int d = 0; d < 16; ++d) { float w = outW[d]; s += w*w; }
        sm[M_S] = s; sm[M_OUTB] = outB[0];
    }
    __syncthreads();

    // ---- branch fusion + positional embedding: 2 threads/token, split by d-half ----
    {
        const int t = tid >> 1, half = tid & 1, dbase = half * 8;
        float acc[8], x[16];
#pragma unroll
        for (int d = 0; d < 8; ++d) acc[d] = sm[OFF_FUSB + dbase + d];
        const float* br[3] = { b1 + ((size_t)b*TC + t)*DD,
                               b2 + ((size_t)b*TC + t)*DD,
                               b3 + ((size_t)b*TC + t)*DD };
#pragma unroll 1
        for (int g = 0; g < 3; ++g) {
#pragma unroll
            for (int c = 0; c < 4; ++c) ld4(x + 4*c, br[g] + 4*c);
#pragma unroll
            for (int d = 0; d < 8; ++d)
                acc[d] += dot16(x, &sm[OFF_FUSW + (dbase + d)*48 + g*16]);
        }
#pragma unroll
        for (int d = 0; d < 8; ++d)
            sm[OFF_X + t*20 + dbase + d] = acc[d] + posE[t*DD + dbase + d];
    }
    __syncthreads();

    const size_t plane = ((size_t)b*NLAY) * 4;  // +l*4+h per use

    // =============== PREFILL: 4 layers over 288 tokens ===============
#pragma unroll 1
    for (int l = 0; l < NLAY; ++l) {
        // QKV projection: 2 threads/token, 24 of 48 outputs each
        {
            const int t = tid >> 1, half = tid & 1, base = half * 24;
            float xr[16], ov[24];
#pragma unroll
            for (int c = 0; c < 4; ++c) ld4(xr+4*c, &sm[OFF_X + t*20 + 4*c]);
            const float* W  = &sm[OFF_WQKV + l*768];
            const float* Bq = &sm[OFF_BQKV + l*48];
#pragma unroll
            for (int j = 0; j < 24; ++j) ov[j] = Bq[base+j] + dot16(xr, W + (base+j)*16);
            float4* gk = (float4*)g_kc;
            float4* gv = (float4*)g_vc;
            if (half == 0) {
                // ov[0..15] = Q, ov[16..23] = K[0..7]
#pragma unroll
                for (int c = 0; c < 4; ++c) st4(&sm[OFF_Q + t*20 + 4*c], ov + 4*c);
                st4(&sm[OFF_K + t*20 + 0], ov + 16);
                st4(&sm[OFF_K + t*20 + 4], ov + 20);
                gk[(plane + l*4 + 0)*LMAX + t] = make_float4(ov[16],ov[17],ov[18],ov[19]);
                gk[(plane + l*4 + 1)*LMAX + t] = make_float4(ov[20],ov[21],ov[22],ov[23]);
            } else {
                // ov[0..7] = K[8..15], ov[8..23] = V[0..15]
                st4(&sm[OFF_K + t*20 +  8], ov + 0);
                st4(&sm[OFF_K + t*20 + 12], ov + 4);
                gk[(plane + l*4 + 2)*LMAX + t] = make_float4(ov[0],ov[1],ov[2],ov[3]);
                gk[(plane + l*4 + 3)*LMAX + t] = make_float4(ov[4],ov[5],ov[6],ov[7]);
#pragma unroll
                for (int c = 0; c < 4; ++c) st4(&sm[OFF_V + t*20 + 4*c], ov + 8 + 4*c);
#pragma unroll
                for (int h = 0; h < 4; ++h)
                    gv[(plane + l*4 + h)*LMAX + t] =
                        make_float4(ov[8+4*h],ov[9+4*h],ov[10+4*h],ov[11+4*h]);
            }
        }
        __syncthreads();

        // causal attention: 1152 (token,head) items, 2 per thread (576 threads).
        // {tid, 1151-tid}: every thread does exactly 289 key-iterations total.
#pragma unroll 1
        for (int it = 0; it < 2; ++it) {
            const int item = it ? (1151 - tid) : tid;
            const int t = item >> 2;
            const int h = item & 3;
            float4 q4 = *(const float4*)&sm[OFF_Q + t*20 + 4*h];
            q4.x *= QSC; q4.y *= QSC; q4.z *= QSC; q4.w *= QSC;
            float s = 0.f, a0 = 0.f, a1 = 0.f, a2 = 0.f, a3 = 0.f;
            const float* kb = &sm[OFF_K + 4*h];
            const float* vb = &sm[OFF_V + 4*h];
#pragma unroll 4
            for (int k = 0; k <= t; ++k) {
                float4 k4 = *(const float4*)(kb + k*20);
                float4 v4 = *(const float4*)(vb + k*20);
                float e = ex2(q4.x*k4.x + q4.y*k4.y + q4.z*k4.z + q4.w*k4.w);
                s += e; a0 += e*v4.x; a1 += e*v4.y; a2 += e*v4.z; a3 += e*v4.w;
            }
            float inv = 1.f / s;
            *(float4*)&sm[OFF_Q + t*20 + 4*h] = make_float4(a0*inv, a1*inv, a2*inv, a3*inv);
        }
        __syncthreads();

        // epilogue: 2 threads/token. Both compute w (out-proj+LN1+cbo+LN2, identical),
        // each accumulates half the FFN hidden units; combine via shfl_xor(1).
        {
            const int t = tid >> 1, half = tid & 1;
            float ar[16], xr[16], w[16];
#pragma unroll
            for (int c = 0; c < 4; ++c) { ld4(ar+4*c, &sm[OFF_Q + t*20 + 4*c]); ld4(xr+4*c, &sm[OFF_X + t*20 + 4*c]); }
            const float* WoL = &sm[OFF_WO + l*256];
#pragma unroll
            for (int d = 0; d < 16; ++d) w[d] = xr[d] + sm[OFF_BO + l*16 + d] + dot16(ar, WoL + d*16);
            lnvec(w, &sm[OFF_LN1G + l*16], &sm[OFF_LN1B + l*16]);
#pragma unroll
            for (int d = 0; d < 16; ++d) w[d] += sm[OFF_CBO + l*16 + d];
            lnvec(w, &sm[OFF_LN2G + l*16], &sm[OFF_LN2B + l*16]);
            // FFN half: j in [half*32, half*32+32)
            const int jb = half * 32;
            const float* W1  = &sm[OFF_FW1 + l*1024 + jb*16];
            const float* W2T = &sm[OFF_FW2 + l*1024 + jb*16];
            float o[16];
#pragma unroll
            for (int d = 0; d < 16; ++d) o[d] = half ? 0.f : (w[d] + sm[OFF_FB2 + l*16 + d]);
#pragma unroll 4
            for (int j = 0; j < 32; ++j) {
                float h = fmaxf(sm[OFF_FB1 + l*64 + jb + j] + dot16(w, W1 + j*16), 0.f);
                float4 u0 = *(const float4*)(W2T + j*16 + 0);
                float4 u1 = *(const float4*)(W2T + j*16 + 4);
                float4 u2 = *(const float4*)(W2T + j*16 + 8);
                float4 u3 = *(const float4*)(W2T + j*16 + 12);
                o[0]+=h*u0.x; o[1]+=h*u0.y; o[2]+=h*u0.z; o[3]+=h*u0.w;
                o[4]+=h*u1.x; o[5]+=h*u1.y; o[6]+=h*u1.z; o[7]+=h*u1.w;
                o[8]+=h*u2.x; o[9]+=h*u2.y; o[10]+=h*u2.z; o[11]+=h*u2.w;
                o[12]+=h*u3.x; o[13]+=h*u3.y; o[14]+=h*u3.z; o[15]+=h*u3.w;
            }
#pragma unroll
            for (int d = 0; d < 16; ++d) o[d] += __shfl_xor_sync(0xffffffffu, o[d], 1);
            if (half == 0) {
                lnvec(o, &sm[OFF_LN3G + l*16], &sm[OFF_LN3B + l*16]);
#pragma unroll
                for (int c = 0; c < 4; ++c) st4(&sm[OFF_X + t*20 + 4*c], o + 4*c);
            }
        }
        __syncthreads();
    }

    // first next-token (prefill last position) + output 0
    if (tid == 0) {
        float acc = sm[M_OUTB];
#pragma unroll
        for (int d = 0; d < 16; ++d) acc += sm[OFF_X + (TC-1)*20 + d] * sm[OFF_OUTW + d];
        sm[M_NT] = acc;
        out[b*TF + 0] = acc * sm[M_S] + sm[M_OUTB];
    }
    __syncthreads();          // all threads: M_NT visible; prefill smem dead

    // warps 8..17 are done: decode runs on the first 256 threads with bar.sync 1,256
    if (tid >= 256) return;

    // =============== DECODE: 11 single-token KV-cache steps ===============
#pragma unroll 1
    for (int step = 1; step < TF; ++step) {
        const int p = TC - 1 + step;   // position of the new token
        if (tid < 16) sm[M_XC + tid] = sm[M_NT] * sm[OFF_OUTW + tid] + posE[p*DD + tid];
        bar256();

#pragma unroll 1
        for (int l = 0; l < NLAY; ++l) {
            // QKV for the single token; K/V appended to global head planes
            if (tid < 48) {
                const int j = tid;
                const float* W = &sm[OFF_WQKV + l*768 + j*16];
                float acc = sm[OFF_BQKV + l*48 + j];
#pragma unroll
                for (int i = 0; i < 16; ++i) acc += sm[M_XC + i] * W[i];
                if (j < 16) {
                    sm[M_QS + j] = acc;
                } else if (j < 32) {
                    const int e = j - 16, h = e >> 2, c = e & 3;
                    g_kc[((plane + l*4 + h)*LMAX + p)*4 + c] = acc;
                } else {
                    const int e = j - 32, h = e >> 2, c = e & 3;
                    g_vc[((plane + l*4 + h)*LMAX + p)*4 + c] = acc;
                }
            }
            bar256();

            // attention over cache: 64 threads/head; all K/V loads issued
            // back-to-back (MLP~10) before the exp/FMA chain consumes them.
            {
                const int h  = tid >> 6;
                const int jj = tid & 63;
                float4 q4 = *(const float4*)&sm[M_QS + 4*h];
                q4.x *= QSC; q4.y *= QSC; q4.z *= QSC; q4.w *= QSC;
                const float4* Kb = (const float4*)g_kc + (plane + l*4 + h)*LMAX;
                const float4* Vb = (const float4*)g_vc + (plane + l*4 + h)*LMAX;
                float4 K4[5], V4[5];
#pragma unroll
                for (int i = 0; i < 5; ++i) {
                    const int k = jj + i*64;
                    if (k <= p) { K4[i] = Kb[k]; V4[i] = Vb[k]; }
                }
                float s = 0.f, a0 = 0.f, a1 = 0.f, a2 = 0.f, a3 = 0.f;
#pragma unroll
                for (int i = 0; i < 5; ++i) {
                    const int k = jj + i*64;
                    if (k <= p) {
                        float e = ex2(q4.x*K4[i].x + q4.y*K4[i].y + q4.z*K4[i].z + q4.w*K4[i].w);
                        s += e; a0 += e*V4[i].x; a1 += e*V4[i].y; a2 += e*V4[i].z; a3 += e*V4[i].w;
                    }
                }
#pragma unroll
                for (int off = 16; off >= 1; off >>= 1) {
                    s  += __shfl_xor_sync(0xffffffffu, s,  off);
                    a0 += __shfl_xor_sync(0xffffffffu, a0, off);
                    a1 += __shfl_xor_sync(0xffffffffu, a1, off);
                    a2 += __shfl_xor_sync(0xffffffffu, a2, off);
                    a3 += __shfl_xor_sync(0xffffffffu, a3, off);
                }
                if ((tid & 31) == 0) {
                    float* r = &sm[M_RED + (tid >> 5)*5];
                    r[0]=s; r[1]=a0; r[2]=a1; r[3]=a2; r[4]=a3;
                }
            }
            bar256();

            // head combine + out-proj + LN1 + cbo + LN2 on warp 0
            if (tid < 32) {
                if (tid < 16) {
                    const int h = tid >> 2, c = tid & 3;
                    const float* r0 = &sm[M_RED + (2*h)*5];
                    const float* r1 = &sm[M_RED + (2*h+1)*5];
                    sm[M_ATT + tid] = (r0[1+c] + r1[1+c]) / (r0[0] + r1[0]);
                }
                __syncwarp(0xffffffffu);
                const int d = tid & 15;
                float w = sm[M_XC + d] + sm[OFF_BO + l*16 + d]
                        + dot16(&sm[M_ATT], &sm[OFF_WO + l*256 + d*16]);
                w = ln16_shfl(w, d, &sm[OFF_LN1G + l*16], &sm[OFF_LN1B + l*16]);
                w += sm[OFF_CBO + l*16 + d];
                w = ln16_shfl(w, d, &sm[OFF_LN2G + l*16], &sm[OFF_LN2B + l*16]);
                sm[M_WC + d] = w;
            }
            bar256();
            if (tid < 64) {   // FFN hidden
                float h = sm[OFF_FB1 + l*64 + tid] + dot16(&sm[M_WC], &sm[OFF_FW1 + l*1024 + tid*16]);
                sm[M_H1 + tid] = fmaxf(h, 0.f);
            }
            bar256();
            if (tid < 32) {   // FFN out (transposed W2) + LN3 -> next layer input
                const int d = tid & 15;
                float o = sm[M_WC + d] + sm[OFF_FB2 + l*16 + d];
                const float* W2T = &sm[OFF_FW2 + l*1024];
#pragma unroll 8
                for (int j = 0; j < 64; ++j) o += sm[M_H1 + j] * W2T[j*16 + d];
                o = ln16_shfl(o, d, &sm[OFF_LN3G + l*16], &sm[OFF_LN3B + l*16]);
                sm[M_XC + d] = o;
            }
            bar256();
        }

        if (tid == 0) {
            float acc = sm[M_OUTB];
#pragma unroll
            for (int d = 0; d < 16; ++d) acc += sm[M_XC + d] * sm[OFF_OUTW + d];
            sm[M_NT] = acc;
            out[b*TF + step] = acc * sm[M_S] + sm[M_OUTB];
        }
        bar256();             // M_NT visible before next step's M_XC write
    }
}

extern "C" void kernel_launch(void* const* d_in, const int* in_sizes, int n_in,
                              void* d_out, int out_size) {
    (void)in_sizes; (void)n_in; (void)out_size;
    cudaFuncSetAttribute(mbar_decoder_kernel,
                         cudaFuncAttributeMaxDynamicSharedMemorySize, SMEM_BYTES);
    mbar_decoder_kernel<<<BB, NTHR, SMEM_BYTES>>>(
        (const float*)d_in[0],  (const float*)d_in[1],  (const float*)d_in[2],
        (const float*)d_in[3],  (const float*)d_in[4],  (const float*)d_in[5],
        (const float*)d_in[6],  (const float*)d_in[7],  (const float*)d_in[8],
        (const float*)d_in[9],  (const float*)d_in[10],
        (const float*)d_in[11], (const float*)d_in[12],
        (const float*)d_in[13], (const float*)d_in[14],
        (const float*)d_in[15], (const float*)d_in[16],
        (const float*)d_in[17], (const float*)d_in[18],
        (const float*)d_in[19], (const float*)d_in[20],
        (const float*)d_in[21], (const float*)d_in[22],
        (float*)d_out);
}